// round 7
// baseline (speedup 1.0000x reference)
#include <cuda_runtime.h>

// PairedKidneyCriticModel: sparse GAT critic, N=4096, H=64, L=3, avg-deg ~33.
// R6: single persistent kernel with software grid barriers (grid.sync idiom),
// grid sized via occupancy query for guaranteed co-residency. Phases:
// mask -> prep -> 3x(gemm -> attn) -> layernorm/value + final reduce.
// Attention uses the proven R4 2-warp-per-node scheme.

#define NN 4096
#define HH 64
#define LL 3
#define NW (NN/32)          // 128 mask words per node
#define MAXD 128            // degree cap (mean 33, observed max ~65)
#define SLOPE 0.2f
#define EPSV 1e-5f
#define MAXGRID 2048

// ---- scratch (device globals; no allocation allowed) ----
__device__ unsigned g_bits[NN * NW];        // 2 MB transposed adjacency bits
__device__ unsigned short g_nbr[NN * MAXD]; // 1 MB neighbor ids (ascending)
__device__ int g_deg[NN];
__device__ float g_x [NN * HH];             // embedding (residual input)
__device__ float g_h [NN * HH];             // hidden state
__device__ float g_hw[NN * HH];             // h @ W (L2-resident, 1 MB)
__device__ float g_src[NN];
__device__ float g_dst[NN];
__device__ float g_part[MAXGRID];
__device__ int g_bars[16];                  // barrier counters; 0 at every launch
                                            // (static init + end-of-kernel reset)

__device__ __forceinline__ float leaky(float e) { return e >= 0.f ? e : SLOPE * e; }

// grid.sync idiom: block bar -> elected release-fence + arrive -> spin -> acquire-fence -> block bar
__device__ __forceinline__ void gbar(int id, int nbt) {
    __syncthreads();
    if (threadIdx.x == 0) {
        __threadfence();
        atomicAdd(&g_bars[id], 1);
        while (((volatile int*)g_bars)[id] < nbt) { }
        __threadfence();
    }
    __syncthreads();
}

__global__ __launch_bounds__(256) void k_fused(
        const float* __restrict__ adj,
        const int* __restrict__ tsp, const float* __restrict__ arr,
        const float* __restrict__ dep, const float* __restrict__ hard,
        const float* __restrict__ w1, const float* __restrict__ b1,
        const float* __restrict__ w2, const float* __restrict__ b2,
        const float* __restrict__ gw, const float* __restrict__ gas,
        const float* __restrict__ gad, const float* __restrict__ gb,
        const float* __restrict__ vw, const float* __restrict__ vb,
        float* __restrict__ out, int nbt) {
    __shared__ __align__(16) char sbuf[(HH * HH + 16 * HH) * 4];  // 20.5 KB union
    __shared__ float sAB[192];
    __shared__ float2 s_sw[4];
    __shared__ float4 s_accbuf[4][16];
    __shared__ float s_warp[8];
    __shared__ float s_red[256];

    const int tid  = threadIdx.x;
    const int warp = tid >> 5, lane = tid & 31;
    const int bid  = blockIdx.x;
    const int gthreads = nbt * 256;
    const int gwarps   = nbt * 8;

    // ================= phase 0: adjacency -> transposed bitmask =================
    // item = (column i, 128-row chunk jc); each word written exactly once.
    for (int flat = bid * 256 + tid; flat < NN * 32; flat += gthreads) {
        int i  = flat & (NN - 1);
        int jc = flat >> 12;
        const float* __restrict__ col = adj + i;
        size_t jbase = (size_t)jc * 128;
        unsigned w0 = 0, w1b = 0, w2b = 0, w3 = 0;
        #pragma unroll 8
        for (int t = 0; t < 32; t++) {
            if (col[(jbase + t) * NN] != 0.f && i != (int)(jbase + t))           w0 |= 1u << t;
            if (col[(jbase + 32 + t) * NN] != 0.f && i != (int)(jbase + 32 + t)) w1b |= 1u << t;
            if (col[(jbase + 64 + t) * NN] != 0.f && i != (int)(jbase + 64 + t)) w2b |= 1u << t;
            if (col[(jbase + 96 + t) * NN] != 0.f && i != (int)(jbase + 96 + t)) w3 |= 1u << t;
        }
        unsigned* __restrict__ dst = &g_bits[i * NW + jc * 4];
        dst[0] = w0; dst[1] = w1b; dst[2] = w2b; dst[3] = w3;
    }
    gbar(0, nbt);

    // ================= phase 1: prep (AB + embed + neighbor lists) =================
    if (tid < 192) {     // collapsed embedding: A = w1@w2 (2xH), B = b1@w2 + b2
        int which = tid >> 6, c = tid & 63;
        float acc = 0.f;
        for (int h = 0; h < HH; h++) {
            float w = w2[h * HH + c];
            float cf = (which == 0) ? w1[h] : (which == 1 ? w1[HH + h] : b1[h]);
            acc += cf * w;
        }
        if (which == 2) acc += b2[c];
        sAB[tid] = acc;
    }
    __syncthreads();
    {
        int raw = tsp[0];
        float ts = (raw > -1000000 && raw < 1000000) ? (float)raw : __int_as_float(raw);
        for (int idx = bid * 256 + tid; idx < NN * HH; idx += gthreads) {
            int i = idx >> 6, c = idx & 63;
            float p = (ts - arr[i]) / (dep[i] - arr[i]);
            g_x[idx] = p * sAB[c] + hard[i] * sAB[HH + c] + sAB[2 * HH + c];
        }
    }
    // neighbor-list compaction: one warp per node, ascending order
    for (int i = bid * 8 + warp; i < NN; i += gwarps) {
        const unsigned* __restrict__ bm = &g_bits[i * NW];
        unsigned short* __restrict__ nb = &g_nbr[i * MAXD];
        int base = 0;
        #pragma unroll
        for (int r = 0; r < 4; r++) {
            unsigned word = bm[r * 32 + lane];
            int cnt = __popc(word);
            int pre = cnt;
            #pragma unroll
            for (int off = 1; off < 32; off <<= 1) {
                int v = __shfl_up_sync(0xffffffffu, pre, off);
                if (lane >= off) pre += v;
            }
            int total = __shfl_sync(0xffffffffu, pre, 31);
            int o = base + pre - cnt;
            while (word) {
                int b = __ffs(word) - 1; word &= word - 1;
                if (o < MAXD) nb[o] = (unsigned short)(r * 1024 + lane * 32 + b);
                o++;
            }
            base += total;
        }
        if (lane == 0) g_deg[i] = (base < MAXD) ? base : MAXD;
    }
    gbar(1, nbt);

    // ================= layers =================
    for (int l = 0; l < LL; l++) {
        // ---- gemm: hw = h @ W[l]; src/dst scores. 256 tiles of 16 rows. ----
        if (bid < 256) {
            float* Ws = (float*)sbuf;                       // 16 KB
            float* hs = (float*)(sbuf + HH * HH * 4);       // 4 KB
            const float* __restrict__ in = (l == 0) ? g_x : g_h;
            const float* __restrict__ W  = gw + l * HH * HH;
            const float* __restrict__ as = gas + l * HH;
            const float* __restrict__ ad = gad + l * HH;
            int rbase = bid * 16;
            #pragma unroll
            for (int t = 0; t < 16; t++) Ws[t * 256 + tid] = W[t * 256 + tid];
            #pragma unroll
            for (int t = 0; t < 4; t++) hs[t * 256 + tid] = in[rbase * HH + t * 256 + tid];
            __syncthreads();

            int r  = tid >> 4;
            int c4 = (tid & 15) * 4;
            float4 acc = make_float4(0.f, 0.f, 0.f, 0.f);
            #pragma unroll
            for (int k = 0; k < HH; k++) {
                float hv = hs[r * HH + k];
                float4 wv = *(const float4*)&Ws[k * HH + c4];
                acc.x += hv * wv.x; acc.y += hv * wv.y;
                acc.z += hv * wv.z; acc.w += hv * wv.w;
            }
            int row = rbase + r;
            *(float4*)&g_hw[row * HH + c4] = acc;

            float ps = acc.x * as[c4] + acc.y * as[c4 + 1] + acc.z * as[c4 + 2] + acc.w * as[c4 + 3];
            float pd = acc.x * ad[c4] + acc.y * ad[c4 + 1] + acc.z * ad[c4 + 2] + acc.w * ad[c4 + 3];
            #pragma unroll
            for (int off = 8; off; off >>= 1) {
                ps += __shfl_down_sync(0xffffffffu, ps, off, 16);
                pd += __shfl_down_sync(0xffffffffu, pd, off, 16);
            }
            if ((tid & 15) == 0) { g_src[row] = ps; g_dst[row] = pd; }
        }
        gbar(2 + 2 * l, nbt);

        // ---- attention: 2 warps per node, 4-quad phase-B split ----
        {
            float2 (*spj)[MAXD] = (float2(*)[MAXD])sbuf;    // 4 KB in union
            const float* __restrict__ b = gb + l * HH;
            int n   = warp >> 1;          // node slot in block (0..3)
            int sub = warp & 1;           // warp within pair
            for (int base = 0; base < NN; base += nbt * 4) {
                int i = base + bid * 4 + n;
                bool act = (i < NN);
                int deg = act ? g_deg[i] : 0;

                if (sub == 0 && act) {
                    float di = g_dst[i];
                    float e0 = leaky(g_src[i] + di);           // self-loop score
                    ushort4 nv = ((const ushort4*)&g_nbr[i * MAXD])[lane];
                    int k0 = lane * 4;
                    int jj[4] = {nv.x, nv.y, nv.z, nv.w};
                    float e[4];
                    float m = e0;
                    #pragma unroll
                    for (int t = 0; t < 4; t++) {
                        e[t] = -1e30f;
                        if (k0 + t < deg) e[t] = leaky(g_src[jj[t]] + di);
                        m = fmaxf(m, e[t]);
                    }
                    #pragma unroll
                    for (int off = 16; off; off >>= 1)
                        m = fmaxf(m, __shfl_xor_sync(0xffffffffu, m, off));
                    float w0 = __expf(e0 - m);
                    float s = 0.f;
                    #pragma unroll
                    for (int t = 0; t < 4; t++) {
                        if (k0 + t < deg) {
                            float p = __expf(e[t] - m);
                            s += p;
                            spj[n][k0 + t] = make_float2(p, __int_as_float(jj[t] * HH));
                        }
                    }
                    #pragma unroll
                    for (int off = 16; off; off >>= 1) s += __shfl_xor_sync(0xffffffffu, s, off);
                    s += w0;
                    if (lane == 0) s_sw[n] = make_float2(w0, 1.0f / s);
                }
                __syncthreads();

                int half = lane >> 4;
                int q    = sub * 2 + half;
                int f4   = (lane & 15) << 2;
                float2 ws = s_sw[n];
                float4 acc = make_float4(0.f, 0.f, 0.f, 0.f);
                if (act) {
                    if (q == 0) {
                        float4 hv = *(const float4*)&g_hw[i * HH + f4];
                        acc.x = ws.x * hv.x; acc.y = ws.x * hv.y;
                        acc.z = ws.x * hv.z; acc.w = ws.x * hv.w;
                    }
                    #pragma unroll 4
                    for (int k = q; k < deg; k += 4) {
                        float2 pj = spj[n][k];
                        const float4 hv = *(const float4*)&g_hw[__float_as_int(pj.y) + f4];
                        acc.x += pj.x * hv.x; acc.y += pj.x * hv.y;
                        acc.z += pj.x * hv.z; acc.w += pj.x * hv.w;
                    }
                }
                acc.x += __shfl_xor_sync(0xffffffffu, acc.x, 16);
                acc.y += __shfl_xor_sync(0xffffffffu, acc.y, 16);
                acc.z += __shfl_xor_sync(0xffffffffu, acc.z, 16);
                acc.w += __shfl_xor_sync(0xffffffffu, acc.w, 16);
                if (sub == 1 && half == 0) s_accbuf[n][lane] = acc;
                __syncthreads();
                if (act && sub == 0 && half == 0) {
                    float4 o2 = s_accbuf[n][lane];
                    float inv = ws.y;
                    float4 o;
                    o.x = (acc.x + o2.x) * inv + b[f4];
                    o.y = (acc.y + o2.y) * inv + b[f4 + 1];
                    o.z = (acc.z + o2.z) * inv + b[f4 + 2];
                    o.w = (acc.w + o2.w) * inv + b[f4 + 3];
                    if (l < LL - 1) {
                        o.x = fmaxf(o.x, 0.f); o.y = fmaxf(o.y, 0.f);
                        o.z = fmaxf(o.z, 0.f); o.w = fmaxf(o.w, 0.f);
                    }
                    *(float4*)&g_h[i * HH + f4] = o;
                }
            }
        }
        gbar(3 + 2 * l, nbt);
    }

    // ================= final: residual + layernorm + value dot =================
    {
        float wsum = 0.f;
        for (int i = bid * 8 + warp; i < NN; i += gwarps) {
            float2 xv = *(const float2*)&g_x[i * HH + 2 * lane];
            float2 hv = *(const float2*)&g_h[i * HH + 2 * lane];
            float v0 = xv.x + hv.x, v1 = xv.y + hv.y;
            float smv = v0 + v1;
            #pragma unroll
            for (int off = 16; off; off >>= 1) smv += __shfl_xor_sync(0xffffffffu, smv, off);
            float mu = smv * (1.0f / 64.0f);
            float d0 = v0 - mu, d1 = v1 - mu;
            float vs = d0 * d0 + d1 * d1;
            #pragma unroll
            for (int off = 16; off; off >>= 1) vs += __shfl_xor_sync(0xffffffffu, vs, off);
            float rstd = rsqrtf(vs * (1.0f / 64.0f) + EPSV);
            float yr = d0 * rstd * vw[2 * lane] + d1 * rstd * vw[2 * lane + 1];
            #pragma unroll
            for (int off = 16; off; off >>= 1) yr += __shfl_xor_sync(0xffffffffu, yr, off);
            wsum += yr;                     // same value in all lanes
        }
        if (lane == 0) s_warp[warp] = wsum;
        __syncthreads();
        if (tid == 0) {
            float t = 0.f;
            #pragma unroll
            for (int w = 0; w < 8; w++) t += s_warp[w];   // fixed order
            g_part[bid] = t;
        }
    }
    gbar(8, nbt);

    if (bid == 0) {
        float v = 0.f;
        for (int k = tid; k < nbt; k += 256) v += g_part[k];   // fixed order
        s_red[tid] = v;
        __syncthreads();
        #pragma unroll
        for (int off = 128; off; off >>= 1) {
            if (tid < off) s_red[tid] += s_red[tid + off];
            __syncthreads();
        }
        if (tid == 0) {
            out[0] = fmaxf(0.0f, s_red[0] * (1.0f / NN) + vb[0]);
            #pragma unroll
            for (int k = 0; k < 16; k++) g_bars[k] = 0;   // replay-safe reset
        }
    }
}

extern "C" void kernel_launch(void* const* d_in, const int* in_sizes, int n_in,
                              void* d_out, int out_size) {
    const float* adj  = (const float*)d_in[0];
    const int*   ts   = (const int*)  d_in[1];
    const float* arr  = (const float*)d_in[2];
    const float* dep  = (const float*)d_in[3];
    const float* hard = (const float*)d_in[4];
    const float* w1 = (const float*)d_in[6];
    const float* b1 = (const float*)d_in[7];
    const float* w2 = (const float*)d_in[8];
    const float* b2 = (const float*)d_in[9];
    const float* gw  = (const float*)d_in[10];
    const float* gas = (const float*)d_in[11];
    const float* gad = (const float*)d_in[12];
    const float* gb  = (const float*)d_in[13];
    const float* vw  = (const float*)d_in[14];
    const float* vb  = (const float*)d_in[15];
    float* out = (float*)d_out;

    int dev = 0, nsm = 0, nb = 0;
    cudaGetDevice(&dev);
    cudaDeviceGetAttribute(&nsm, cudaDevAttrMultiProcessorCount, dev);
    cudaOccupancyMaxActiveBlocksPerMultiprocessor(&nb, k_fused, 256, 0);
    if (nb < 1) nb = 1;
    int grid = nsm * nb;
    if (grid > MAXGRID) grid = MAXGRID;
    if (grid > 256) grid = (grid / 8) * 8;   // keep node-slot math tidy
    if (grid < 256) grid = 256;              // 256 guaranteed co-resident (>=2/SM fits)

    k_fused<<<grid, 256>>>(adj, ts, arr, dep, hard, w1, b1, w2, b2,
                           gw, gas, gad, gb, vw, vb, out, grid);
}

// round 8
// speedup vs baseline: 1.6187x; 1.6187x over previous
#include <cuda_runtime.h>

// PairedKidneyCriticModel: sparse GAT critic, N=4096, H=64, L=3, avg-deg ~33.
// R7: R4 structure (proven) + PDL launch-gap hiding + fusions:
//   k_mask -> k_prep(nbr only) -> k_gemm0(+AB+embed) -> k_attn0 -> k_gemm1
//   -> k_attn1 -> k_gemm2 -> k_attn2(+layernorm/value/global-reduce)

#define NN 4096
#define HH 64
#define LL 3
#define NW (NN/32)          // 128 mask words per node
#define MAXD 128            // degree cap (mean 33, observed max ~65)
#define SLOPE 0.2f
#define EPSV 1e-5f

#define PDL_WAIT() asm volatile("griddepcontrol.wait;" ::: "memory")
#define PDL_TRIG() asm volatile("griddepcontrol.launch_dependents;" ::: "memory")

// ---- scratch (device globals; no allocation allowed) ----
__device__ unsigned g_bits[NN * NW];        // 2 MB transposed adjacency bits
__device__ unsigned short g_nbr[NN * MAXD]; // 1 MB neighbor ids (ascending)
__device__ int g_deg[NN];
__device__ float g_x [NN * HH];             // embedding (residual input)
__device__ float g_h [NN * HH];             // hidden state
__device__ float g_hw[NN * HH];             // h @ W (L2-resident, 1 MB)
__device__ float g_src[NN];
__device__ float g_dst[NN];
__device__ float g_part[1024];
__device__ int g_cnt;

__device__ __forceinline__ float leaky(float e) { return e >= 0.f ? e : SLOPE * e; }

// ---- 1. mask build: thread per (column i, 128-row chunk); words written once ----
__global__ __launch_bounds__(256) void k_mask(const float* __restrict__ adj) {
    int ib = blockIdx.x & 15;          // 16 i-blocks of 256 columns
    int jc = blockIdx.x >> 4;          // 32 j-chunks of 128 rows
    int i  = ib * 256 + threadIdx.x;
    const float* __restrict__ col = adj + i;
    size_t jbase = (size_t)jc * 128;
    unsigned w0 = 0, w1 = 0, w2 = 0, w3 = 0;
    #pragma unroll 8
    for (int t = 0; t < 32; t++) {
        if (col[(jbase + t) * NN] != 0.f && i != (int)(jbase + t))            w0 |= 1u << t;
        if (col[(jbase + 32 + t) * NN] != 0.f && i != (int)(jbase + 32 + t))  w1 |= 1u << t;
        if (col[(jbase + 64 + t) * NN] != 0.f && i != (int)(jbase + 64 + t))  w2 |= 1u << t;
        if (col[(jbase + 96 + t) * NN] != 0.f && i != (int)(jbase + 96 + t))  w3 |= 1u << t;
    }
    unsigned* __restrict__ dst = &g_bits[i * NW + jc * 4];
    dst[0] = w0; dst[1] = w1; dst[2] = w2; dst[3] = w3;
    PDL_TRIG();
}

// ---- 2. neighbor-list compaction: one warp per node, ascending order ----
__global__ __launch_bounds__(256) void k_prep() {
    PDL_WAIT();                          // g_bits must be complete
    int warp = threadIdx.x >> 5, lane = threadIdx.x & 31;
    int i = blockIdx.x * 8 + warp;       // 512 blocks
    const unsigned* __restrict__ bm = &g_bits[i * NW];
    unsigned short* __restrict__ nb = &g_nbr[i * MAXD];
    int base = 0;
    #pragma unroll
    for (int r = 0; r < 4; r++) {
        unsigned word = bm[r * 32 + lane];
        int cnt = __popc(word);
        int pre = cnt;
        #pragma unroll
        for (int off = 1; off < 32; off <<= 1) {
            int v = __shfl_up_sync(0xffffffffu, pre, off);
            if (lane >= off) pre += v;
        }
        int total = __shfl_sync(0xffffffffu, pre, 31);
        int o = base + pre - cnt;
        while (word) {
            int b = __ffs(word) - 1; word &= word - 1;
            if (o < MAXD) nb[o] = (unsigned short)(r * 1024 + lane * 32 + b);
            o++;
        }
        base += total;
    }
    if (lane == 0) g_deg[i] = (base < MAXD) ? base : MAXD;
    if (blockIdx.x == 0 && threadIdx.x == 0) g_cnt = 0;   // replay-safe reset
    PDL_TRIG();
}

// ---- 3. gemm (+ fused AB/embed when l==0): hw = in @ W[l]; src/dst scores ----
__global__ __launch_bounds__(256) void k_gemm(
        const float* __restrict__ gw, const float* __restrict__ gas,
        const float* __restrict__ gad, int l,
        const float* __restrict__ w1, const float* __restrict__ b1,
        const float* __restrict__ w2, const float* __restrict__ b2,
        const int* __restrict__ tsp, const float* __restrict__ arr,
        const float* __restrict__ dep, const float* __restrict__ hard) {
    __shared__ float Ws[HH * HH];     // 16 KB
    __shared__ float hs[16 * HH];     // 4 KB
    __shared__ float sAB[192];
    const float* __restrict__ W  = gw + l * HH * HH;
    const float* __restrict__ as = gas + l * HH;
    const float* __restrict__ ad = gad + l * HH;
    int tid = threadIdx.x;            // 256
    int rbase = blockIdx.x * 16;      // 256 blocks
    int r  = tid >> 4;
    int c4 = (tid & 15) * 4;
    int row = rbase + r;

    // weight tile load reads only harness inputs — safe pre-wait preamble
    #pragma unroll
    for (int t = 0; t < 16; t++) Ws[t * 256 + tid] = W[t * 256 + tid];

    if (l == 0) {
        // fused collapsed embedding + per-row embed (no dependency on prior kernels)
        if (tid < 192) {
            int which = tid >> 6, c = tid & 63;
            float acc = 0.f;
            for (int h = 0; h < HH; h++) {
                float w = w2[h * HH + c];
                float cf = (which == 0) ? w1[h] : (which == 1 ? w1[HH + h] : b1[h]);
                acc += cf * w;
            }
            if (which == 2) acc += b2[c];
            sAB[tid] = acc;
        }
        __syncthreads();
        int raw = tsp[0];
        float ts = (raw > -1000000 && raw < 1000000) ? (float)raw : __int_as_float(raw);
        float p = (ts - arr[row]) / (dep[row] - arr[row]);
        float hd = hard[row];
        float4 xv;
        xv.x = p * sAB[c4]     + hd * sAB[HH + c4]     + sAB[2 * HH + c4];
        xv.y = p * sAB[c4 + 1] + hd * sAB[HH + c4 + 1] + sAB[2 * HH + c4 + 1];
        xv.z = p * sAB[c4 + 2] + hd * sAB[HH + c4 + 2] + sAB[2 * HH + c4 + 2];
        xv.w = p * sAB[c4 + 3] + hd * sAB[HH + c4 + 3] + sAB[2 * HH + c4 + 3];
        *(float4*)&hs[r * HH + c4] = xv;
        *(float4*)&g_x[row * HH + c4] = xv;
        __syncthreads();
    } else {
        PDL_WAIT();                   // g_h from previous attention
        #pragma unroll
        for (int t = 0; t < 4; t++) hs[t * 256 + tid] = g_h[rbase * HH + t * 256 + tid];
        __syncthreads();
    }

    float4 acc = make_float4(0.f, 0.f, 0.f, 0.f);
    #pragma unroll
    for (int k = 0; k < HH; k++) {
        float hv = hs[r * HH + k];
        float4 wv = *(const float4*)&Ws[k * HH + c4];
        acc.x += hv * wv.x; acc.y += hv * wv.y;
        acc.z += hv * wv.z; acc.w += hv * wv.w;
    }
    *(float4*)&g_hw[row * HH + c4] = acc;

    float ps = acc.x * as[c4] + acc.y * as[c4 + 1] + acc.z * as[c4 + 2] + acc.w * as[c4 + 3];
    float pd = acc.x * ad[c4] + acc.y * ad[c4 + 1] + acc.z * ad[c4 + 2] + acc.w * ad[c4 + 3];
    #pragma unroll
    for (int off = 8; off; off >>= 1) {
        ps += __shfl_down_sync(0xffffffffu, ps, off, 16);
        pd += __shfl_down_sync(0xffffffffu, pd, off, 16);
    }
    if ((tid & 15) == 0) { g_src[row] = ps; g_dst[row] = pd; }
    PDL_TRIG();
}

// shared attention body: computes h-row (in o, valid on sub==0/half==0 lanes);
// returns via pointer whether this lane holds output
__device__ __forceinline__ float4 attn_body(int i, int n, int sub, int lane,
                                            const float* __restrict__ b, int l,
                                            float2 (*spj)[MAXD], float2* s_sw,
                                            float4 (*s_accbuf)[16], bool* holds) {
    int deg = g_deg[i];
    if (sub == 0) {
        float di = g_dst[i];
        float e0 = leaky(g_src[i] + di);            // self-loop score
        ushort4 nv = ((const ushort4*)&g_nbr[i * MAXD])[lane];
        int k0 = lane * 4;
        int jj[4] = {nv.x, nv.y, nv.z, nv.w};
        float e[4];
        float m = e0;
        #pragma unroll
        for (int t = 0; t < 4; t++) {
            e[t] = -1e30f;
            if (k0 + t < deg) e[t] = leaky(g_src[jj[t]] + di);
            m = fmaxf(m, e[t]);
        }
        #pragma unroll
        for (int off = 16; off; off >>= 1)
            m = fmaxf(m, __shfl_xor_sync(0xffffffffu, m, off));
        float w0 = __expf(e0 - m);
        float s = 0.f;
        #pragma unroll
        for (int t = 0; t < 4; t++) {
            if (k0 + t < deg) {
                float p = __expf(e[t] - m);
                s += p;
                spj[n][k0 + t] = make_float2(p, __int_as_float(jj[t] * HH));
            }
        }
        #pragma unroll
        for (int off = 16; off; off >>= 1) s += __shfl_xor_sync(0xffffffffu, s, off);
        s += w0;
        if (lane == 0) s_sw[n] = make_float2(w0, 1.0f / s);
    }
    __syncthreads();

    int half = lane >> 4;
    int q    = sub * 2 + half;
    int f4   = (lane & 15) << 2;
    float2 ws = s_sw[n];
    float4 acc = make_float4(0.f, 0.f, 0.f, 0.f);
    if (q == 0) {
        float4 hv = *(const float4*)&g_hw[i * HH + f4];
        acc.x = ws.x * hv.x; acc.y = ws.x * hv.y;
        acc.z = ws.x * hv.z; acc.w = ws.x * hv.w;
    }
    #pragma unroll 4
    for (int k = q; k < deg; k += 4) {
        float2 pj = spj[n][k];
        const float4 hv = *(const float4*)&g_hw[__float_as_int(pj.y) + f4];
        acc.x += pj.x * hv.x; acc.y += pj.x * hv.y;
        acc.z += pj.x * hv.z; acc.w += pj.x * hv.w;
    }
    acc.x += __shfl_xor_sync(0xffffffffu, acc.x, 16);
    acc.y += __shfl_xor_sync(0xffffffffu, acc.y, 16);
    acc.z += __shfl_xor_sync(0xffffffffu, acc.z, 16);
    acc.w += __shfl_xor_sync(0xffffffffu, acc.w, 16);
    if (sub == 1 && half == 0) s_accbuf[n][lane] = acc;
    __syncthreads();
    *holds = (sub == 0 && half == 0);
    float4 o = make_float4(0.f, 0.f, 0.f, 0.f);
    if (*holds) {
        float4 o2 = s_accbuf[n][lane];
        float inv = ws.y;
        o.x = (acc.x + o2.x) * inv + b[f4];
        o.y = (acc.y + o2.y) * inv + b[f4 + 1];
        o.z = (acc.z + o2.z) * inv + b[f4 + 2];
        o.w = (acc.w + o2.w) * inv + b[f4 + 3];
    }
    return o;
}

// ---- 4. attention layers 0,1: relu + store g_h ----
__global__ __launch_bounds__(256) void k_attn(const float* __restrict__ gb, int l) {
    __shared__ float2 spj[4][MAXD];
    __shared__ float2 s_sw[4];
    __shared__ float4 s_accbuf[4][16];
    PDL_WAIT();
    int warp = threadIdx.x >> 5, lane = threadIdx.x & 31;
    int n = warp >> 1, sub = warp & 1;
    int i = blockIdx.x * 4 + n;           // 1024 blocks
    bool holds;
    float4 o = attn_body(i, n, sub, lane, gb + l * HH, l, spj, s_sw, s_accbuf, &holds);
    if (holds) {
        o.x = fmaxf(o.x, 0.f); o.y = fmaxf(o.y, 0.f);
        o.z = fmaxf(o.z, 0.f); o.w = fmaxf(o.w, 0.f);
        *(float4*)&g_h[i * HH + ((lane & 15) << 2)] = o;
    }
    PDL_TRIG();
}

// ---- 5. attention layer 2 fused with residual+layernorm+value+global reduce ----
__global__ __launch_bounds__(256) void k_attn2(const float* __restrict__ gb,
                                               const float* __restrict__ vw,
                                               const float* __restrict__ vb,
                                               float* __restrict__ out) {
    __shared__ float2 spj[4][MAXD];
    __shared__ float2 s_sw[4];
    __shared__ float4 s_accbuf[4][16];
    __shared__ float s_node[4];
    __shared__ int islast;
    __shared__ float s_red[256];
    PDL_WAIT();
    int warp = threadIdx.x >> 5, lane = threadIdx.x & 31;
    int n = warp >> 1, sub = warp & 1;
    int i = blockIdx.x * 4 + n;           // 1024 blocks
    bool holds;
    float4 o = attn_body(i, n, sub, lane, gb + 2 * HH, 2, spj, s_sw, s_accbuf, &holds);

    if (holds) {                          // 16 lanes of warp sub==0 per node
        int f4 = (lane & 15) << 2;
        float4 xv = *(const float4*)&g_x[i * HH + f4];
        float v0 = xv.x + o.x, v1 = xv.y + o.y, v2 = xv.z + o.z, v3 = xv.w + o.w;
        float sm = v0 + v1 + v2 + v3;
        #pragma unroll
        for (int off = 8; off; off >>= 1) sm += __shfl_xor_sync(0x0000ffffu, sm, off, 16);
        float mu = sm * (1.0f / 64.0f);
        float d0 = v0 - mu, d1 = v1 - mu, d2 = v2 - mu, d3 = v3 - mu;
        float vs = d0 * d0 + d1 * d1 + d2 * d2 + d3 * d3;
        #pragma unroll
        for (int off = 8; off; off >>= 1) vs += __shfl_xor_sync(0x0000ffffu, vs, off, 16);
        float rstd = rsqrtf(vs * (1.0f / 64.0f) + EPSV);
        float yr = (d0 * vw[f4] + d1 * vw[f4 + 1] + d2 * vw[f4 + 2] + d3 * vw[f4 + 3]) * rstd;
        #pragma unroll
        for (int off = 8; off; off >>= 1) yr += __shfl_xor_sync(0x0000ffffu, yr, off, 16);
        if (lane == 0) s_node[n] = yr;
    }
    __syncthreads();
    if (threadIdx.x == 0) {
        float t = s_node[0] + s_node[1] + s_node[2] + s_node[3];   // fixed order
        g_part[blockIdx.x] = t;
        __threadfence();
        islast = (atomicAdd(&g_cnt, 1) == 1023);
    }
    __syncthreads();
    if (islast) {
        __threadfence();
        int tid = threadIdx.x;
        float v = 0.f;
        #pragma unroll
        for (int k = 0; k < 4; k++) v += g_part[tid + k * 256];    // fixed order
        s_red[tid] = v;
        __syncthreads();
        #pragma unroll
        for (int off = 128; off; off >>= 1) {
            if (tid < off) s_red[tid] += s_red[tid + off];
            __syncthreads();
        }
        if (tid == 0)
            out[0] = fmaxf(0.0f, s_red[0] * (1.0f / NN) + vb[0]);
    }
}

static void launch_pdl(void* func, dim3 grid, dim3 block, void** args) {
    cudaLaunchConfig_t cfg = {};
    cfg.gridDim = grid;
    cfg.blockDim = block;
    cudaLaunchAttribute attr[1];
    attr[0].id = cudaLaunchAttributeProgrammaticStreamSerialization;
    attr[0].val.programmaticStreamSerializationAllowed = 1;
    cfg.attrs = attr;
    cfg.numAttrs = 1;
    cudaLaunchKernelExC(&cfg, func, args);
}

extern "C" void kernel_launch(void* const* d_in, const int* in_sizes, int n_in,
                              void* d_out, int out_size) {
    const float* adj  = (const float*)d_in[0];
    const int*   ts   = (const int*)  d_in[1];
    const float* arr  = (const float*)d_in[2];
    const float* dep  = (const float*)d_in[3];
    const float* hard = (const float*)d_in[4];
    const float* w1 = (const float*)d_in[6];
    const float* b1 = (const float*)d_in[7];
    const float* w2 = (const float*)d_in[8];
    const float* b2 = (const float*)d_in[9];
    const float* gw  = (const float*)d_in[10];
    const float* gas = (const float*)d_in[11];
    const float* gad = (const float*)d_in[12];
    const float* gb  = (const float*)d_in[13];
    const float* vw  = (const float*)d_in[14];
    const float* vb  = (const float*)d_in[15];
    float* out = (float*)d_out;

    k_mask<<<512, 256>>>(adj);

    {   void* a[] = {};
        launch_pdl((void*)k_prep, dim3(512), dim3(256), a); }

    for (int l = 0; l < LL; l++) {
        void* ga[] = {(void*)&gw, (void*)&gas, (void*)&gad, (void*)&l,
                      (void*)&w1, (void*)&b1, (void*)&w2, (void*)&b2,
                      (void*)&ts, (void*)&arr, (void*)&dep, (void*)&hard};
        launch_pdl((void*)k_gemm, dim3(256), dim3(256), ga);
        if (l < LL - 1) {
            void* aa[] = {(void*)&gb, (void*)&l};
            launch_pdl((void*)k_attn, dim3(1024), dim3(256), aa);
        } else {
            void* aa[] = {(void*)&gb, (void*)&vw, (void*)&vb, (void*)&out};
            launch_pdl((void*)k_attn2, dim3(1024), dim3(256), aa);
        }
    }
}